// round 11
// baseline (speedup 1.0000x reference)
#include <cuda_runtime.h>
#include <cstdint>

#define T_STEPS 256
#define BATCH   8
#define NPROBES 4
#define NTHREADS 1024
#define CLUSTER 4
#define NCTAS   (BATCH * CLUSTER)
#define FULLM   0xffffffffu

typedef unsigned long long ull;

// ---------- f32x2 packed helpers (sm_103a) ----------
__device__ __forceinline__ ull pack2(float lo, float hi) {
    ull r; asm("mov.b64 %0, {%1, %2};" : "=l"(r) : "f"(lo), "f"(hi)); return r;
}
__device__ __forceinline__ void unpack2(ull a, float& lo, float& hi) {
    asm("mov.b64 {%0, %1}, %2;" : "=f"(lo), "=f"(hi) : "l"(a));
}
__device__ __forceinline__ ull add2(ull a, ull b) {
    ull r; asm("add.rn.f32x2 %0, %1, %2;" : "=l"(r) : "l"(a), "l"(b)); return r;
}
__device__ __forceinline__ ull fma2(ull a, ull b, ull c) {
    ull r; asm("fma.rn.f32x2 %0, %1, %2, %3;" : "=l"(r) : "l"(a), "l"(b), "l"(c)); return r;
}

// ---------- cluster / mbarrier helpers ----------
__device__ __forceinline__ uint32_t smem_u32(const void* p) {
    uint32_t a;
    asm("{ .reg .u64 t; cvta.to.shared.u64 t, %1; cvt.u32.u64 %0, t; }" : "=r"(a) : "l"(p));
    return a;
}
__device__ __forceinline__ uint32_t mapa_u32(uint32_t addr, uint32_t rank) {
    uint32_t r; asm("mapa.shared::cluster.u32 %0, %1, %2;" : "=r"(r) : "r"(addr), "r"(rank));
    return r;
}
__device__ __forceinline__ void st_cluster_v2(uint32_t addr, ull a, ull b) {
    asm volatile("st.shared::cluster.v2.u64 [%0], {%1, %2};" :: "r"(addr), "l"(a), "l"(b) : "memory");
}
__device__ __forceinline__ void mbar_init(uint32_t addr, uint32_t cnt) {
    asm volatile("mbarrier.init.shared.b64 [%0], %1;" :: "r"(addr), "r"(cnt) : "memory");
}
__device__ __forceinline__ void mbar_arrive_local(uint32_t addr) {
    asm volatile("mbarrier.arrive.release.cta.shared::cta.b64 _, [%0];" :: "r"(addr) : "memory");
}
__device__ __forceinline__ void mbar_arrive_remote(uint32_t addr) {
    asm volatile("mbarrier.arrive.release.cluster.shared::cluster.b64 _, [%0];" :: "r"(addr) : "memory");
}
__device__ __forceinline__ void mbar_wait_cta(uint32_t addr, uint32_t ph) {
    uint32_t done;
    do {
        asm volatile("{\n\t.reg .pred p;\n\t"
                     "mbarrier.try_wait.parity.acquire.cta.shared::cta.b64 p, [%1], %2, 0x989680;\n\t"
                     "selp.b32 %0, 1, 0, p;\n\t}"
                     : "=r"(done) : "r"(addr), "r"(ph) : "memory");
    } while (!done);
}
__device__ __forceinline__ void mbar_wait_cluster(uint32_t addr, uint32_t ph) {
    uint32_t done;
    do {
        asm volatile("{\n\t.reg .pred p;\n\t"
                     "mbarrier.try_wait.parity.acquire.cluster.shared::cta.b64 p, [%1], %2, 0x989680;\n\t"
                     "selp.b32 %0, 1, 0, p;\n\t}"
                     : "=r"(done) : "r"(addr), "r"(ph) : "memory");
    } while (!done);
}
__device__ __forceinline__ void cluster_sync() {
    asm volatile("barrier.cluster.arrive.aligned;" ::: "memory");
    asm volatile("barrier.cluster.wait.aligned;"   ::: "memory");
}

__device__ float    g_psum[NPROBES] = {0.f, 0.f, 0.f, 0.f};
__device__ unsigned g_ticket        = 0u;

// dynamic smem (bytes):
//   [0, 32768)      halo  : ull[2][32][64]  one row per warp, buf = t&1
//   [32768, 33792)  rbufA : ull[2][64]      row from rank-1 (my "above")
//   [33792, 34816)  rbufB : ull[2][64]      row from rank+1 (my "below")
//   [34816, 35840)  xsh   : float[256]
//   [35840, 36352)  wmbar : ull[32][2]
#define OFF_RBUFA 32768
#define OFF_RBUFB 33792
#define OFF_XSH   34816
#define OFF_WMBAR 35840
#define SMEM_BYTES 36368

__global__ __launch_bounds__(NTHREADS, 1) __cluster_dims__(CLUSTER, 1, 1)
void wave_fused_kernel(const float* __restrict__ x,
                       const float* __restrict__ c,
                       const int* __restrict__ probes_i32,
                       float* __restrict__ out)
{
    extern __shared__ char smem_raw[];
    ull*   halo  = reinterpret_cast<ull*>(smem_raw);
    ull*   rbufA = reinterpret_cast<ull*>(smem_raw + OFF_RBUFA);
    ull*   rbufB = reinterpret_cast<ull*>(smem_raw + OFF_RBUFB);
    float* xsh   = reinterpret_cast<float*>(smem_raw + OFF_XSH);

    const uint32_t smem_base  = smem_u32(smem_raw);
    const uint32_t wmbar_base = smem_base + OFF_WMBAR;   // wmbar[w][bi] at +(w*2+bi)*8

    uint32_t rank; asm("mov.u32 %0, %%cluster_ctarank;" : "=r"(rank));
    const int b   = blockIdx.x >> 2;          // batch = cluster id
    const int tid = threadIdx.x;
    const int w   = tid >> 5;                 // warp 0..31 : local row w
    const int l   = tid & 31;                 // lane       : cols 4l..4l+3
    const int c0  = l << 2;
    const int gr  = (int)rank * 32 + w;       // my global row

    // constants (reference-exact, folded by invd)
    const float dtb   = 0.5f * 0.005f;
    const float cy2s  = -1.0f - dtb;                   // -1.0025
    const float denom = 4.0f + (0.5f * 0.005f) / 0.5f; // 4.005
    const float invd  = 1.0f / denom;

    const ull NEG4  = pack2(-4.0f, -4.0f);
    const ull CY2P  = pack2(cy2s * invd, cy2s * invd);
    const ull TWO2P = pack2(2.0f * invd, 2.0f * invd);

    for (int t = tid; t < T_STEPS; t += NTHREADS)
        xsh[t] = x[t * BATCH + b];
    for (int i = tid; i < 2 * 32 * 64; i += NTHREADS)
        halo[i] = 0ull;
    for (int i = tid; i < 2 * 64; i += NTHREADS) { rbufA[i] = 0ull; rbufB[i] = 0ull; }

    // kk' = 0.25*c^2*invd for my single row
    ull kkx, kky, y1lo, y1hi, y2lo, y2hi;
    {
        float4 cv = *reinterpret_cast<const float4*>(&c[gr * 128 + c0]);
        kkx = pack2(0.25f * cv.x * cv.x * invd, 0.25f * cv.y * cv.y * invd);
        kky = pack2(0.25f * cv.z * cv.z * invd, 0.25f * cv.w * cv.w * invd);
        y1lo = 0ull; y1hi = 0ull; y2lo = 0ull; y2hi = 0ull;
    }

    // ---- probe decoding (runtime dtype detection: int32 vs int64) ----
    int pxv[NPROBES], pyv[NPROBES];
    {
        int odd_or = probes_i32[1] | probes_i32[3] | probes_i32[5] | probes_i32[7];
        if (odd_or == 0) {
#pragma unroll
            for (int p = 0; p < NPROBES; p++) { pxv[p] = probes_i32[4 * p]; pyv[p] = probes_i32[4 * p + 2]; }
        } else {
#pragma unroll
            for (int p = 0; p < NPROBES; p++) { pxv[p] = probes_i32[2 * p]; pyv[p] = probes_i32[2 * p + 1]; }
        }
    }
    float pacc[NPROBES];
    int   pidx[NPROBES];          // comp 0..3, or -1
    bool  pown = false;
#pragma unroll
    for (int p = 0; p < NPROBES; p++) {
        pacc[p] = 0.f;
        bool mine = (pxv[p] == gr) && (pyv[p] >= c0) && (pyv[p] < c0 + 4);
        pidx[p] = mine ? (pyv[p] - c0) : -1;
        pown = pown || mine;
    }

    // source (64,64): global row 64 = rank 2, w 0; col 64 -> lane 16, comp 0
    const bool src_owner = (rank == 2) && (w == 0) && (l == 16);

    // cluster seam roles
    const bool top_edge = (w == 0)  && (rank > 0);            // reads rbufA, pushes up
    const bool bot_edge = (w == 31) && (rank < CLUSTER - 1);  // reads rbufB, pushes down
    const uint32_t up_rank = (rank > 0) ? rank - 1 : 0;
    const uint32_t dn_rank = (rank < CLUSTER - 1) ? rank + 1 : rank;
    const uint32_t peer_up_rbuf  = mapa_u32(smem_base + OFF_RBUFB, up_rank);
    const uint32_t peer_up_mbar  = mapa_u32(wmbar_base + (31 * 2) * 8, up_rank);
    const uint32_t peer_dn_rbuf  = mapa_u32(smem_base + OFF_RBUFA, dn_rank);
    const uint32_t peer_dn_mbar  = mapa_u32(wmbar_base + (0 * 2) * 8, dn_rank);

    const uint32_t my_mbar = wmbar_base + (w * 2) * 8;
    const uint32_t up_mbar = wmbar_base + ((w - 1) * 2) * 8;
    const uint32_t dn_mbar = wmbar_base + ((w + 1) * 2) * 8;

    // init my two mbars: ONE elected arrive per producer warp feeding me
    if (l == 0) {
        uint32_t cnt = 0;
        cnt += (w > 0 || rank > 0) ? 1 : 0;               // above producer
        cnt += (w < 31 || rank < CLUSTER - 1) ? 1 : 0;    // below producer
        mbar_init(my_mbar, cnt);
        mbar_init(my_mbar + 8, cnt);
    }
    const bool has_remote = top_edge || bot_edge;

    __syncthreads();   // local init + smem zero done
    cluster_sync();    // visible cluster-wide before any remote arrive

    for (int t = 0; t < T_STEPS; t++) {
        const int rdbuf = (t + 1) & 1;   // buffer with step t-1 data
        const int wrbuf = t & 1;

        // -------- precompute everything independent of neighbor rows --------
        const ull v_lo = y1lo, v_hi = y1hi;
        float vx, vy, vz, vw;
        unpack2(v_lo, vx, vy);
        unpack2(v_hi, vz, vw);

        float lf = __shfl_up_sync(FULLM, vw, 1);
        float rt = __shfl_down_sync(FULLM, vx, 1);
        if (l == 0)  lf = 0.f;
        if (l == 31) rt = 0.f;

        const ull P2   = pack2(vy, vz);
        const ull h_lo = add2(pack2(lf, vx), P2);
        const ull h_hi = add2(P2, pack2(vw, rt));
        const ull base_lo = fma2(CY2P, y2lo, TWO2P);
        const ull base_hi = fma2(CY2P, y2hi, TWO2P);

        // -------- wait for both neighbors' step-(t-1) data --------
        if (t > 0) {
            const uint32_t mb = my_mbar + ((t - 1) & 1) * 8;
            const uint32_t ph = ((t - 1) >> 1) & 1;
            if (has_remote) mbar_wait_cluster(mb, ph);
            else            mbar_wait_cta(mb, ph);
        }

        // neighbor rows
        ull ab_lo = 0, ab_hi = 0, bl_lo = 0, bl_hi = 0;
        if (w > 0) {
            ulonglong2 h = *reinterpret_cast<const ulonglong2*>(
                &halo[rdbuf * 2048 + (w - 1) * 64 + 2 * l]);
            ab_lo = h.x; ab_hi = h.y;
        } else if (top_edge) {
            ulonglong2 h = *reinterpret_cast<const ulonglong2*>(&rbufA[rdbuf * 64 + 2 * l]);
            ab_lo = h.x; ab_hi = h.y;
        }
        if (w < 31) {
            ulonglong2 h = *reinterpret_cast<const ulonglong2*>(
                &halo[rdbuf * 2048 + (w + 1) * 64 + 2 * l]);
            bl_lo = h.x; bl_hi = h.y;
        } else if (bot_edge) {
            ulonglong2 h = *reinterpret_cast<const ulonglong2*>(&rbufB[rdbuf * 64 + 2 * l]);
            bl_lo = h.x; bl_hi = h.y;
        }

        // -------- short post-wakeup chain --------
        // association preserved: (ab+bl) + (P1+P2), then fma(-4,v), then fma(kk,lap,base)
        ull s_lo  = add2(add2(ab_lo, bl_lo), h_lo);
        ull s_hi  = add2(add2(ab_hi, bl_hi), h_hi);
        ull nv_lo = fma2(kkx, fma2(NEG4, v_lo, s_lo), base_lo);
        ull nv_hi = fma2(kky, fma2(NEG4, v_hi, s_hi), base_hi);

        if (src_owner) {
            float a, b2; unpack2(nv_lo, a, b2);
            nv_lo = pack2(a + xsh[t], b2);
        }

        y2lo = v_lo;  y2hi = v_hi;
        y1lo = nv_lo; y1hi = nv_hi;

        // -------- publish + elected arrives (skip after last step) --------
        if (t < T_STEPS - 1) {
            ulonglong2 rv; rv.x = y1lo; rv.y = y1hi;
            *reinterpret_cast<ulonglong2*>(&halo[wrbuf * 2048 + w * 64 + 2 * l]) = rv;
            if (top_edge)
                st_cluster_v2(peer_up_rbuf + (wrbuf * 64 + 2 * l) * 8, y1lo, y1hi);
            if (bot_edge)
                st_cluster_v2(peer_dn_rbuf + (wrbuf * 64 + 2 * l) * 8, y1lo, y1hi);

            __syncwarp();   // all lanes' stores visible to electing lanes

            if (l == 0 && w > 0)     mbar_arrive_local(up_mbar + wrbuf * 8);
            if (l == 1 && w < 31)    mbar_arrive_local(dn_mbar + wrbuf * 8);
            if (l == 2 && top_edge)  mbar_arrive_remote(peer_up_mbar + wrbuf * 8);
            if (l == 3 && bot_edge)  mbar_arrive_remote(peer_dn_mbar + wrbuf * 8);
        }

        // probe accumulation (<=4 owning threads; off the critical handoff path)
        if (pown) {
#pragma unroll
            for (int p = 0; p < NPROBES; p++) {
                if (pidx[p] >= 0) {
                    float a, bf, val = 0.f;
                    switch (pidx[p]) {
                        case 0: unpack2(y1lo, a, bf); val = a;  break;
                        case 1: unpack2(y1lo, a, bf); val = bf; break;
                        case 2: unpack2(y1hi, a, bf); val = a;  break;
                        case 3: unpack2(y1hi, a, bf); val = bf; break;
                    }
                    pacc[p] += val * val;
                }
            }
        }
    }

#pragma unroll
    for (int p = 0; p < NPROBES; p++)
        if (pidx[p] >= 0) atomicAdd(&g_psum[p], pacc[p]);

    // fused finalization: last of 32 CTAs reduces, writes out, resets globals
    __syncthreads();
    __threadfence();
    if (tid == 0) {
        unsigned ticket = atomicAdd(&g_ticket, 1u);
        if (ticket == NCTAS - 1) {
            float v[NPROBES];
            float s = 0.f;
#pragma unroll
            for (int p = 0; p < NPROBES; p++) { v[p] = atomicAdd(&g_psum[p], 0.0f); s += v[p]; }
#pragma unroll
            for (int p = 0; p < NPROBES; p++) {
                out[p] = v[p] / s;
                atomicExch(&g_psum[p], 0.0f);
            }
            atomicExch(&g_ticket, 0u);
        }
    }
}

extern "C" void kernel_launch(void* const* d_in, const int* in_sizes, int n_in,
                              void* d_out, int out_size)
{
    const float* x      = (const float*)d_in[0];   // (256, 8) f32
    const float* c      = (const float*)d_in[1];   // (128, 128) f32
    const int*   probes = (const int*)d_in[2];     // (4, 2) i32/i64 — detected in-kernel
    float*       out    = (float*)d_out;           // (4,) f32

    cudaFuncSetAttribute(wave_fused_kernel,
                         cudaFuncAttributeMaxDynamicSharedMemorySize, SMEM_BYTES);

    wave_fused_kernel<<<NCTAS, NTHREADS, SMEM_BYTES>>>(x, c, probes, out);
}

// round 12
// speedup vs baseline: 1.2219x; 1.2219x over previous
#include <cuda_runtime.h>
#include <cstdint>

#define T_STEPS 256
#define BATCH   8
#define NPROBES 4
#define CLUSTER 8
#define ROWS_PER_CTA (128 / CLUSTER)      // 16
#define NWARPS  ROWS_PER_CTA              // 16
#define NTHREADS (NWARPS * 32)            // 512
#define NCTAS   (BATCH * CLUSTER)         // 64
#define FULLM   0xffffffffu

typedef unsigned long long ull;

// ---------- f32x2 packed helpers (sm_103a) ----------
__device__ __forceinline__ ull pack2(float lo, float hi) {
    ull r; asm("mov.b64 %0, {%1, %2};" : "=l"(r) : "f"(lo), "f"(hi)); return r;
}
__device__ __forceinline__ void unpack2(ull a, float& lo, float& hi) {
    asm("mov.b64 {%0, %1}, %2;" : "=f"(lo), "=f"(hi) : "l"(a));
}
__device__ __forceinline__ ull add2(ull a, ull b) {
    ull r; asm("add.rn.f32x2 %0, %1, %2;" : "=l"(r) : "l"(a), "l"(b)); return r;
}
__device__ __forceinline__ ull fma2(ull a, ull b, ull c) {
    ull r; asm("fma.rn.f32x2 %0, %1, %2, %3;" : "=l"(r) : "l"(a), "l"(b), "l"(c)); return r;
}

// ---------- cluster / mbarrier helpers ----------
__device__ __forceinline__ uint32_t smem_u32(const void* p) {
    uint32_t a;
    asm("{ .reg .u64 t; cvta.to.shared.u64 t, %1; cvt.u32.u64 %0, t; }" : "=r"(a) : "l"(p));
    return a;
}
__device__ __forceinline__ uint32_t mapa_u32(uint32_t addr, uint32_t rank) {
    uint32_t r; asm("mapa.shared::cluster.u32 %0, %1, %2;" : "=r"(r) : "r"(addr), "r"(rank));
    return r;
}
__device__ __forceinline__ void st_cluster_v2(uint32_t addr, ull a, ull b) {
    asm volatile("st.shared::cluster.v2.u64 [%0], {%1, %2};" :: "r"(addr), "l"(a), "l"(b) : "memory");
}
__device__ __forceinline__ void mbar_init(uint32_t addr, uint32_t cnt) {
    asm volatile("mbarrier.init.shared.b64 [%0], %1;" :: "r"(addr), "r"(cnt) : "memory");
}
__device__ __forceinline__ void mbar_arrive_local(uint32_t addr) {
    asm volatile("mbarrier.arrive.release.cta.shared::cta.b64 _, [%0];" :: "r"(addr) : "memory");
}
__device__ __forceinline__ void mbar_arrive_remote(uint32_t addr) {
    asm volatile("mbarrier.arrive.release.cluster.shared::cluster.b64 _, [%0];" :: "r"(addr) : "memory");
}
__device__ __forceinline__ void mbar_wait_cta(uint32_t addr, uint32_t ph) {
    uint32_t done;
    do {
        asm volatile("{\n\t.reg .pred p;\n\t"
                     "mbarrier.try_wait.parity.acquire.cta.shared::cta.b64 p, [%1], %2, 0x989680;\n\t"
                     "selp.b32 %0, 1, 0, p;\n\t}"
                     : "=r"(done) : "r"(addr), "r"(ph) : "memory");
    } while (!done);
}
__device__ __forceinline__ void mbar_wait_cluster(uint32_t addr, uint32_t ph) {
    uint32_t done;
    do {
        asm volatile("{\n\t.reg .pred p;\n\t"
                     "mbarrier.try_wait.parity.acquire.cluster.shared::cta.b64 p, [%1], %2, 0x989680;\n\t"
                     "selp.b32 %0, 1, 0, p;\n\t}"
                     : "=r"(done) : "r"(addr), "r"(ph) : "memory");
    } while (!done);
}
__device__ __forceinline__ void cluster_sync() {
    asm volatile("barrier.cluster.arrive.aligned;" ::: "memory");
    asm volatile("barrier.cluster.wait.aligned;"   ::: "memory");
}

__device__ float    g_psum[NPROBES] = {0.f, 0.f, 0.f, 0.f};
__device__ unsigned g_ticket        = 0u;

// dynamic smem (bytes):
//   [0, 16384)      halo  : ull[2][16][64]  one row per warp, buf = t&1
//   [16384, 17408)  rbufA : ull[2][64]      row from rank-1 (my "above")
//   [17408, 18432)  rbufB : ull[2][64]      row from rank+1 (my "below")
//   [18432, 19456)  xsh   : float[256]
//   [19456, 19712)  wmbar : ull[16][2]
#define OFF_RBUFA 16384
#define OFF_RBUFB 17408
#define OFF_XSH   18432
#define OFF_WMBAR 19456
#define SMEM_BYTES 19728

__global__ __launch_bounds__(NTHREADS, 1) __cluster_dims__(CLUSTER, 1, 1)
void wave_fused_kernel(const float* __restrict__ x,
                       const float* __restrict__ c,
                       const int* __restrict__ probes_i32,
                       float* __restrict__ out)
{
    extern __shared__ char smem_raw[];
    ull*   halo  = reinterpret_cast<ull*>(smem_raw);
    ull*   rbufA = reinterpret_cast<ull*>(smem_raw + OFF_RBUFA);
    ull*   rbufB = reinterpret_cast<ull*>(smem_raw + OFF_RBUFB);
    float* xsh   = reinterpret_cast<float*>(smem_raw + OFF_XSH);

    const uint32_t smem_base  = smem_u32(smem_raw);
    const uint32_t wmbar_base = smem_base + OFF_WMBAR;   // wmbar[w][bi] at +(w*2+bi)*8

    uint32_t rank; asm("mov.u32 %0, %%cluster_ctarank;" : "=r"(rank));
    const int b   = blockIdx.x / CLUSTER;     // batch = cluster id
    const int tid = threadIdx.x;
    const int w   = tid >> 5;                 // warp 0..15 : local row w
    const int l   = tid & 31;                 // lane       : cols 4l..4l+3
    const int c0  = l << 2;
    const int gr  = (int)rank * ROWS_PER_CTA + w;   // my global row

    // constants (reference-exact, folded by invd)
    const float dtb   = 0.5f * 0.005f;
    const float cy2s  = -1.0f - dtb;                   // -1.0025
    const float denom = 4.0f + (0.5f * 0.005f) / 0.5f; // 4.005
    const float invd  = 1.0f / denom;

    const ull NEG4  = pack2(-4.0f, -4.0f);
    const ull CY2P  = pack2(cy2s * invd, cy2s * invd);
    const ull TWO2P = pack2(2.0f * invd, 2.0f * invd);

    for (int t = tid; t < T_STEPS; t += NTHREADS)
        xsh[t] = x[t * BATCH + b];
    for (int i = tid; i < 2 * ROWS_PER_CTA * 64; i += NTHREADS)
        halo[i] = 0ull;
    for (int i = tid; i < 2 * 64; i += NTHREADS) { rbufA[i] = 0ull; rbufB[i] = 0ull; }

    // kk' = 0.25*c^2*invd for my single row
    ull kkx, kky, y1lo, y1hi, y2lo, y2hi;
    {
        float4 cv = *reinterpret_cast<const float4*>(&c[gr * 128 + c0]);
        kkx = pack2(0.25f * cv.x * cv.x * invd, 0.25f * cv.y * cv.y * invd);
        kky = pack2(0.25f * cv.z * cv.z * invd, 0.25f * cv.w * cv.w * invd);
        y1lo = 0ull; y1hi = 0ull; y2lo = 0ull; y2hi = 0ull;
    }

    // ---- probe decoding (runtime dtype detection: int32 vs int64) ----
    int pxv[NPROBES], pyv[NPROBES];
    {
        int odd_or = probes_i32[1] | probes_i32[3] | probes_i32[5] | probes_i32[7];
        if (odd_or == 0) {
#pragma unroll
            for (int p = 0; p < NPROBES; p++) { pxv[p] = probes_i32[4 * p]; pyv[p] = probes_i32[4 * p + 2]; }
        } else {
#pragma unroll
            for (int p = 0; p < NPROBES; p++) { pxv[p] = probes_i32[2 * p]; pyv[p] = probes_i32[2 * p + 1]; }
        }
    }
    float pacc[NPROBES];
    int   pidx[NPROBES];          // comp 0..3, or -1
    bool  pown = false;
#pragma unroll
    for (int p = 0; p < NPROBES; p++) {
        pacc[p] = 0.f;
        bool mine = (pxv[p] == gr) && (pyv[p] >= c0) && (pyv[p] < c0 + 4);
        pidx[p] = mine ? (pyv[p] - c0) : -1;
        pown = pown || mine;
    }

    // source (64,64): global row 64 = rank 4, w 0; col 64 -> lane 16, comp 0
    const bool src_owner = (rank == 4) && (w == 0) && (l == 16);

    // cluster seam roles
    const bool top_edge = (w == 0)              && (rank > 0);            // reads rbufA, pushes up
    const bool bot_edge = (w == NWARPS - 1)     && (rank < CLUSTER - 1);  // reads rbufB, pushes down
    const uint32_t up_rank = (rank > 0) ? rank - 1 : 0;
    const uint32_t dn_rank = (rank < CLUSTER - 1) ? rank + 1 : rank;
    // rank r w0    pushes row to rank r-1's rbufB, arrives rank r-1 wmbar[NWARPS-1]
    // rank r wLast pushes row to rank r+1's rbufA, arrives rank r+1 wmbar[0]
    const uint32_t peer_up_rbuf  = mapa_u32(smem_base + OFF_RBUFB, up_rank);
    const uint32_t peer_up_mbar  = mapa_u32(wmbar_base + ((NWARPS - 1) * 2) * 8, up_rank);
    const uint32_t peer_dn_rbuf  = mapa_u32(smem_base + OFF_RBUFA, dn_rank);
    const uint32_t peer_dn_mbar  = mapa_u32(wmbar_base + (0 * 2) * 8, dn_rank);

    const uint32_t my_mbar = wmbar_base + (w * 2) * 8;
    const uint32_t up_mbar = wmbar_base + ((w - 1) * 2) * 8;
    const uint32_t dn_mbar = wmbar_base + ((w + 1) * 2) * 8;

    // init my two mbars: arrivals = 32 per producer warp feeding me
    if (l == 0) {
        uint32_t cnt = 0;
        cnt += (w > 0 || rank > 0) ? 32 : 0;                         // above producer
        cnt += (w < NWARPS - 1 || rank < CLUSTER - 1) ? 32 : 0;      // below producer
        mbar_init(my_mbar, cnt);
        mbar_init(my_mbar + 8, cnt);
    }
    const bool has_remote = top_edge || bot_edge;

    __syncthreads();   // local init + smem zero done
    cluster_sync();    // visible cluster-wide before any remote arrive

    for (int t = 0; t < T_STEPS; t++) {
        const int rdbuf = (t + 1) & 1;   // buffer with step t-1 data
        const int wrbuf = t & 1;

        // single HW-sleep wait for both neighbors' step-(t-1) data
        if (t > 0) {
            const uint32_t mb = my_mbar + ((t - 1) & 1) * 8;
            const uint32_t ph = ((t - 1) >> 1) & 1;
            if (has_remote) mbar_wait_cluster(mb, ph);
            else            mbar_wait_cta(mb, ph);
        }

        // neighbor rows
        ull ab_lo = 0, ab_hi = 0, bl_lo = 0, bl_hi = 0;
        if (w > 0) {
            ulonglong2 h = *reinterpret_cast<const ulonglong2*>(
                &halo[rdbuf * (ROWS_PER_CTA * 64) + (w - 1) * 64 + 2 * l]);
            ab_lo = h.x; ab_hi = h.y;
        } else if (top_edge) {
            ulonglong2 h = *reinterpret_cast<const ulonglong2*>(&rbufA[rdbuf * 64 + 2 * l]);
            ab_lo = h.x; ab_hi = h.y;
        }
        if (w < NWARPS - 1) {
            ulonglong2 h = *reinterpret_cast<const ulonglong2*>(
                &halo[rdbuf * (ROWS_PER_CTA * 64) + (w + 1) * 64 + 2 * l]);
            bl_lo = h.x; bl_hi = h.y;
        } else if (bot_edge) {
            ulonglong2 h = *reinterpret_cast<const ulonglong2*>(&rbufB[rdbuf * 64 + 2 * l]);
            bl_lo = h.x; bl_hi = h.y;
        }

        // update my row
        {
            const ull v_lo = y1lo, v_hi = y1hi;
            float vx, vy, vz, vw;
            unpack2(v_lo, vx, vy);
            unpack2(v_hi, vz, vw);

            float lf = __shfl_up_sync(FULLM, vw, 1);
            float rt = __shfl_down_sync(FULLM, vx, 1);
            if (l == 0)  lf = 0.f;
            if (l == 31) rt = 0.f;

            const ull P1 = pack2(lf, vx);
            const ull P2 = pack2(vy, vz);
            const ull P3 = pack2(vw, rt);

            ull lap_lo = add2(add2(ab_lo, bl_lo), add2(P1, P2));
            lap_lo = fma2(NEG4, v_lo, lap_lo);
            ull lap_hi = add2(add2(ab_hi, bl_hi), add2(P2, P3));
            lap_hi = fma2(NEG4, v_hi, lap_hi);

            ull nv_lo = fma2(kkx, lap_lo, fma2(CY2P, y2lo, TWO2P));
            ull nv_hi = fma2(kky, lap_hi, fma2(CY2P, y2hi, TWO2P));

            if (src_owner) {
                float a, b2; unpack2(nv_lo, a, b2);
                nv_lo = pack2(a + xsh[t], b2);
            }

            y2lo = v_lo;  y2hi = v_hi;
            y1lo = nv_lo; y1hi = nv_hi;
        }

        // probe accumulation (<=4 owning threads)
        if (pown) {
#pragma unroll
            for (int p = 0; p < NPROBES; p++) {
                if (pidx[p] >= 0) {
                    float a, bf, val = 0.f;
                    switch (pidx[p]) {
                        case 0: unpack2(y1lo, a, bf); val = a;  break;
                        case 1: unpack2(y1lo, a, bf); val = bf; break;
                        case 2: unpack2(y1hi, a, bf); val = a;  break;
                        case 3: unpack2(y1hi, a, bf); val = bf; break;
                    }
                    pacc[p] += val * val;
                }
            }
        }

        // publish my row + arrive on consumers (skip after last step)
        if (t < T_STEPS - 1) {
            ulonglong2 rv; rv.x = y1lo; rv.y = y1hi;
            *reinterpret_cast<ulonglong2*>(
                &halo[wrbuf * (ROWS_PER_CTA * 64) + w * 64 + 2 * l]) = rv;

            if (w > 0)          mbar_arrive_local(up_mbar + wrbuf * 8);
            if (w < NWARPS - 1) mbar_arrive_local(dn_mbar + wrbuf * 8);

            if (top_edge) {
                st_cluster_v2(peer_up_rbuf + (wrbuf * 64 + 2 * l) * 8, y1lo, y1hi);
                mbar_arrive_remote(peer_up_mbar + wrbuf * 8);
            }
            if (bot_edge) {
                st_cluster_v2(peer_dn_rbuf + (wrbuf * 64 + 2 * l) * 8, y1lo, y1hi);
                mbar_arrive_remote(peer_dn_mbar + wrbuf * 8);
            }
        }
    }

#pragma unroll
    for (int p = 0; p < NPROBES; p++)
        if (pidx[p] >= 0) atomicAdd(&g_psum[p], pacc[p]);

    // fused finalization: last of 64 CTAs reduces, writes out, resets globals
    __syncthreads();
    __threadfence();
    if (tid == 0) {
        unsigned ticket = atomicAdd(&g_ticket, 1u);
        if (ticket == NCTAS - 1) {
            float v[NPROBES];
            float s = 0.f;
#pragma unroll
            for (int p = 0; p < NPROBES; p++) { v[p] = atomicAdd(&g_psum[p], 0.0f); s += v[p]; }
#pragma unroll
            for (int p = 0; p < NPROBES; p++) {
                out[p] = v[p] / s;
                atomicExch(&g_psum[p], 0.0f);
            }
            atomicExch(&g_ticket, 0u);
        }
    }
}

extern "C" void kernel_launch(void* const* d_in, const int* in_sizes, int n_in,
                              void* d_out, int out_size)
{
    const float* x      = (const float*)d_in[0];   // (256, 8) f32
    const float* c      = (const float*)d_in[1];   // (128, 128) f32
    const int*   probes = (const int*)d_in[2];     // (4, 2) i32/i64 — detected in-kernel
    float*       out    = (float*)d_out;           // (4,) f32

    cudaFuncSetAttribute(wave_fused_kernel,
                         cudaFuncAttributeMaxDynamicSharedMemorySize, SMEM_BYTES);

    wave_fused_kernel<<<NCTAS, NTHREADS, SMEM_BYTES>>>(x, c, probes, out);
}